// round 3
// baseline (speedup 1.0000x reference)
#include <cuda_runtime.h>
#include <cuda_bf16.h>
#include <cstdint>

// Problem dims (fixed by the dataset)
#define Bz 32
#define Tz 1000
#define Hz 512
#define Vz 2048
#define Lz 100
#define BTz (Bz*Tz)
#define Sz (2*Lz+1)           // 201
#define NLAB 101              // blank + L labels
#define NEGINF (-1e10f)

// ---------------- device scratch (static: no allocation) ----------------
__device__ __nv_bfloat16 g_Wbf[Vz*Hz];         // W in bf16 (2 MB)
__device__ __nv_bfloat16 g_Wlab[Bz*128*Hz];    // gathered label W rows (padded to 128)
__device__ float         g_blab[Bz*128];       // gathered label biases
__device__ float         g_lab[(size_t)BTz*NLAB]; // label log-probs (logit+bias-lse)
__device__ float         g_lossb[Bz];

// ---------------- ptx helpers (compute_103-safe: no tcgen05) ----------------
__device__ __forceinline__ uint32_t smem_u32(const void* p) {
    uint32_t a;
    asm("{ .reg .u64 t; cvta.to.shared.u64 t, %1; cvt.u32.u64 %0, t; }" : "=r"(a) : "l"(p));
    return a;
}
__device__ __forceinline__ void mma16816(float* c, uint32_t a0, uint32_t a1,
                                         uint32_t a2, uint32_t a3,
                                         uint32_t b0, uint32_t b1) {
    asm volatile(
        "mma.sync.aligned.m16n8k16.row.col.f32.bf16.bf16.f32 "
        "{%0,%1,%2,%3}, {%4,%5,%6,%7}, {%8,%9}, {%0,%1,%2,%3};\n"
        : "+f"(c[0]), "+f"(c[1]), "+f"(c[2]), "+f"(c[3])
        : "r"(a0), "r"(a1), "r"(a2), "r"(a3), "r"(b0), "r"(b1));
}
#define LDSM_X4(r0, r1, r2, r3, addr) \
    asm volatile("ldmatrix.sync.aligned.m8n8.x4.shared.b16 {%0,%1,%2,%3}, [%4];" \
        : "=r"(r0), "=r"(r1), "=r"(r2), "=r"(r3) : "r"(addr))
#define CP_ASYNC16(dst, src) \
    asm volatile("cp.async.cg.shared.global [%0], [%1], 16;" :: "r"(dst), "l"(src) : "memory")
#define CP_COMMIT() asm volatile("cp.async.commit_group;" ::: "memory")
#define CP_WAIT(n) asm volatile("cp.async.wait_group " #n ";" ::: "memory")

// ---------------- smem layout for k_main ----------------
#define A_STR 520                       // bf16 per A row (512 + 8 pad) -> 1040B, 16B-mult
#define A_BYTES (128*A_STR*2)           // 133120
#define W_STR 72                        // bf16 per W row (64 + 8 pad) -> 144B
#define WSTAGE_BYTES (128*W_STR*2)      // 18432
#define NSTAGE 4
#define MAIN_SMEM (A_BYTES + NSTAGE*WSTAGE_BYTES)   // 206848
#define NTILES (17*8)                   // 16 V-chunks + 1 label chunk, 8 K-subtiles each

// ---------------- kernel 1: fp32 -> bf16 conversion (W only) ----------------
__global__ void k_convertW(const float* __restrict__ Wm) {
    const int nW2 = (Vz*Hz)/2;
    __nv_bfloat162* W2 = reinterpret_cast<__nv_bfloat162*>(g_Wbf);
    const float2* w2 = reinterpret_cast<const float2*>(Wm);
    for (int i = blockIdx.x*blockDim.x + threadIdx.x; i < nW2; i += gridDim.x*blockDim.x) {
        float2 v = w2[i]; W2[i] = __floats2bfloat162_rn(v.x, v.y);
    }
}

// ---------------- kernel 2: gather label W rows + biases ----------------
__global__ void k_gather(const float* __restrict__ bias, const int* __restrict__ ys) {
    int idx = blockIdx.x;            // b*128 + j
    int b = idx >> 7, j = idx & 127;
    int v = (j == 0) ? 0 : ((j <= Lz) ? ys[b*Lz + j - 1] : -1);
    uint4* dst = reinterpret_cast<uint4*>(g_Wlab + (size_t)idx*Hz);
    if (v >= 0) {
        const uint4* src = reinterpret_cast<const uint4*>(g_Wbf + (size_t)v*Hz);
        dst[threadIdx.x] = src[threadIdx.x];
    } else {
        dst[threadIdx.x] = make_uint4(0u,0u,0u,0u);
    }
    if (threadIdx.x == 0) g_blab[idx] = (v >= 0) ? bias[v] : 0.f;
}

// ---------------- kernel 3: fused GEMM + online LSE + label log-probs ----------------
// Grid: Bz*8 CTAs. CTA = (b, tchunk): 125 time rows (padded to 128 via clamp;
// duplicate writes are idempotent). A[128x512] bf16 in smem (converted inline).
// Loop 17 N-chunks of 128 (16 vocab + 1 label), each 8 K-subtiles of 64 via a
// 4-stage cp.async ring. ldmatrix.x4 feeds mma.sync.m16n8k16. Online LSE in
// registers; final lse replicated per quad feeds the label epilogue directly.
__global__ __launch_bounds__(256, 1)
void k_main(const float* __restrict__ eouts, const float* __restrict__ bias) {
    extern __shared__ char smc[];
    const uint32_t sb = smem_u32(smc);
    const uint32_t RB = sb + A_BYTES;           // W ring base
    const int tid = threadIdx.x;
    const int w = tid >> 5, lane = tid & 31, g = lane >> 2, tig = lane & 3;
    const int b = blockIdx.x >> 3;
    const int t0 = (blockIdx.x & 7) * 125;

    // ---- A tile: 128 rows x 512, fp32->bf16 inline, clamped t ----
    __nv_bfloat16* As = reinterpret_cast<__nv_bfloat16*>(smc);
    for (int e = tid; e < 128*64; e += 256) {
        int row = e >> 6, c = e & 63;
        int t = t0 + row; if (t > Tz-1) t = Tz-1;
        const float4* src = reinterpret_cast<const float4*>(eouts + (size_t)(b*Tz + t)*Hz + c*8);
        float4 v0 = src[0], v1 = src[1];
        __nv_bfloat162 p0 = __floats2bfloat162_rn(v0.x, v0.y);
        __nv_bfloat162 p1 = __floats2bfloat162_rn(v0.z, v0.w);
        __nv_bfloat162 p2 = __floats2bfloat162_rn(v1.x, v1.y);
        __nv_bfloat162 p3 = __floats2bfloat162_rn(v1.z, v1.w);
        uint4 pk = make_uint4(*reinterpret_cast<uint32_t*>(&p0), *reinterpret_cast<uint32_t*>(&p1),
                              *reinterpret_cast<uint32_t*>(&p2), *reinterpret_cast<uint32_t*>(&p3));
        *reinterpret_cast<uint4*>(As + row*A_STR + c*8) = pk;
    }

    // ---- W tile loader: tile j -> stage j&3 (cp.async, 4x16B per thread) ----
    auto load_tile = [&](int j) {
        const int ncj = j >> 3, kcj = j & 7;
        const __nv_bfloat16* base = (ncj < 16) ? (g_Wbf + (size_t)(ncj*128)*Hz)
                                               : (g_Wlab + (size_t)b*128*Hz);
        const uint32_t dbase = RB + (uint32_t)(j & 3) * WSTAGE_BYTES;
        #pragma unroll
        for (int q = 0; q < 4; q++) {
            int idx = q*256 + tid;
            int row = idx >> 3, c = idx & 7;
            const void* gp = base + (size_t)row*Hz + kcj*64 + c*8;
            CP_ASYNC16(dbase + (uint32_t)(row*144 + c*16),
                       (const void*)__cvta_generic_to_global(gp));
        }
        CP_COMMIT();
    };
    load_tile(0); load_tile(1); load_tile(2);

    // ---- ldmatrix lane address bases ----
    // A: lanes 0-7 rows m0..7 k0 | 8-15 rows m0+8..15 k0 | 16-23 rows m0..7 k0+8 | 24-31 rows +8 k0+8
    const uint32_t aBase = sb + (uint32_t)((w*16 + (lane & 15))*A_STR*2) + (uint32_t)(((lane >> 4) & 1)*16);
    // B: lanes 0-7 rows n..n+7 k0 | 8-15 same rows k0+8 | 16-23 rows n+8.. k0 | 24-31 rows +8 k0+8
    const uint32_t bLane = (uint32_t)(((lane & 7) + ((lane >> 4) << 3))*144 + (((lane >> 3) & 1)*16));

    float M0 = -3e38f, S0 = 0.f, M1 = -3e38f, S1 = 0.f;
    float lse0 = 0.f, lse1 = 0.f;

    #pragma unroll 1
    for (int nc = 0; nc < 17; nc++) {
        float acc[16][4];
        #pragma unroll
        for (int i2 = 0; i2 < 16; i2++) { acc[i2][0]=0.f; acc[i2][1]=0.f; acc[i2][2]=0.f; acc[i2][3]=0.f; }

        #pragma unroll 1
        for (int kc = 0; kc < 8; kc++) {
            const int i = nc*8 + kc;
            if (i < NTILES-2)       { CP_WAIT(2); }
            else if (i == NTILES-2) { CP_WAIT(1); }
            else                    { CP_WAIT(0); }
            __syncthreads();
            if (i + 3 < NTILES) load_tile(i + 3);

            const uint32_t stage = RB + (uint32_t)(i & 3) * WSTAGE_BYTES;
            const uint32_t bA = stage + bLane;
            #pragma unroll
            for (int ks = 0; ks < 4; ks++) {
                uint32_t a0, a1, a2, a3;
                LDSM_X4(a0, a1, a2, a3, aBase + (uint32_t)(kc*128 + ks*32));
                #pragma unroll
                for (int p = 0; p < 8; p++) {
                    uint32_t b0, b1, b2, b3;
                    LDSM_X4(b0, b1, b2, b3, bA + (uint32_t)(p*2304 + ks*32));
                    mma16816(acc[2*p],   a0, a1, a2, a3, b0, b1);
                    mma16816(acc[2*p+1], a0, a1, a2, a3, b2, b3);
                }
            }
        }

        if (nc < 16) {
            // ---- vocab chunk epilogue: bias + online LSE (quad-replicated) ----
            const int vbase = nc * 128;
            float m0 = -3e38f, m1 = -3e38f;
            #pragma unroll
            for (int nt = 0; nt < 16; nt++) {
                int v = vbase + nt*8 + 2*tig;
                float bb0 = __ldg(&bias[v]), bb1 = __ldg(&bias[v+1]);
                acc[nt][0] += bb0; acc[nt][1] += bb1; acc[nt][2] += bb0; acc[nt][3] += bb1;
                m0 = fmaxf(m0, fmaxf(acc[nt][0], acc[nt][1]));
                m1 = fmaxf(m1, fmaxf(acc[nt][2], acc[nt][3]));
            }
            float s0 = 0.f, s1 = 0.f;
            #pragma unroll
            for (int nt = 0; nt < 16; nt++) {
                s0 += __expf(acc[nt][0]-m0) + __expf(acc[nt][1]-m0);
                s1 += __expf(acc[nt][2]-m1) + __expf(acc[nt][3]-m1);
            }
            #pragma unroll
            for (int off = 1; off <= 2; off <<= 1) {
                float mo = __shfl_xor_sync(0xffffffffu, m0, off);
                float so = __shfl_xor_sync(0xffffffffu, s0, off);
                float mn = fmaxf(m0, mo);
                s0 = s0*__expf(m0-mn) + so*__expf(mo-mn); m0 = mn;
                mo = __shfl_xor_sync(0xffffffffu, m1, off);
                so = __shfl_xor_sync(0xffffffffu, s1, off);
                mn = fmaxf(m1, mo);
                s1 = s1*__expf(m1-mn) + so*__expf(mo-mn); m1 = mn;
            }
            { float mn = fmaxf(M0, m0); S0 = S0*__expf(M0-mn) + s0*__expf(m0-mn); M0 = mn; }
            { float mn = fmaxf(M1, m1); S1 = S1*__expf(M1-mn) + s1*__expf(m1-mn); M1 = mn; }
            if (nc == 15) { lse0 = M0 + __logf(S0); lse1 = M1 + __logf(S1); }
        } else {
            // ---- label chunk epilogue: lp = logit + blab - lse -> g_lab ----
            int rA = w*16 + g, rB = rA + 8;
            int tA = t0 + rA; if (tA > Tz-1) tA = Tz-1;
            int tB = t0 + rB; if (tB > Tz-1) tB = Tz-1;
            float* labA = g_lab + (size_t)(b*Tz + tA)*NLAB;
            float* labB = g_lab + (size_t)(b*Tz + tB)*NLAB;
            #pragma unroll
            for (int nt = 0; nt < 16; nt++) {
                int c0 = nt*8 + 2*tig, c1 = c0 + 1;
                if (c0 < NLAB) {
                    float bb0 = g_blab[b*128 + c0];
                    labA[c0] = acc[nt][0] + bb0 - lse0;
                    labB[c0] = acc[nt][2] + bb0 - lse1;
                }
                if (c1 < NLAB) {
                    float bb1 = g_blab[b*128 + c1];
                    labA[c1] = acc[nt][1] + bb1 - lse0;
                    labB[c1] = acc[nt][3] + bb1 - lse1;
                }
            }
        }
    }
}

// ---------------- kernel 4: CTC forward DP ----------------
__global__ __launch_bounds__(256) void k_dp(const int* __restrict__ ys,
                                            const int* __restrict__ elens,
                                            const int* __restrict__ ylens) {
    __shared__ float abuf[2][224];
    const int b = blockIdx.x;
    const int s = threadIdx.x;
    const int elen = elens[b];
    const int ylen = ylens[b];
    const bool active = (s < Sz);
    const bool valid = (s < 2*ylen + 1);
    const int j = (s & 1) ? ((s >> 1) + 1) : 0;
    bool skip = false;
    if ((s & 1) && s >= 3 && s < Sz) {
        skip = (ys[b*Lz + (s >> 1)] != ys[b*Lz + (s >> 1) - 1]);
    }
    const float* lab = g_lab + (size_t)b*Tz*NLAB;

    if (active) {
        float a = (s < 2) ? lab[j] : NEGINF;
        if (!valid) a = NEGINF;
        abuf[0][s] = a;
    }
    float lp_cur = active ? lab[(size_t)1*NLAB + j] : 0.f;
    float lp_nxt = (active && 2 < elen) ? lab[(size_t)2*NLAB + j] : 0.f;
    __syncthreads();

    int pp = 0;
    for (int t = 1; t < elen; t++) {
        float nv = NEGINF;
        if (active && valid) {
            float x0 = abuf[pp][s];
            float x1 = (s >= 1) ? abuf[pp][s-1] : NEGINF;
            float x2 = skip ? abuf[pp][s-2] : NEGINF;
            float m = fmaxf(x0, fmaxf(x1, x2));
            float sum = __expf(x0-m) + __expf(x1-m) + __expf(x2-m);
            nv = m + __logf(sum) + lp_cur;
        }
        lp_cur = lp_nxt;
        lp_nxt = (active && (t + 2) < elen) ? lab[(size_t)(t+2)*NLAB + j] : 0.f;
        if (active) abuf[pp ^ 1][s] = nv;
        __syncthreads();
        pp ^= 1;
    }

    if (s == 0) {
        float last = abuf[pp][2*ylen];
        float prev = abuf[pp][2*ylen - 1];
        float m = fmaxf(last, prev);
        float loss = -(m + __logf(__expf(last-m) + __expf(prev-m)));
        g_lossb[b] = (loss < -0.5f*NEGINF) ? loss : 0.f;
    }
}

// ---------------- kernel 5: deterministic finalize ----------------
__global__ void k_final(float* __restrict__ out) {
    if (threadIdx.x == 0 && blockIdx.x == 0) {
        float s = 0.f;
        for (int b = 0; b < Bz; b++) s += g_lossb[b];
        out[0] = s / (float)Bz;
    }
}

// ---------------- entry ----------------
extern "C" void kernel_launch(void* const* d_in, const int* in_sizes, int n_in,
                              void* d_out, int out_size) {
    const float* eouts = (const float*)d_in[0];
    const float* W     = (const float*)d_in[1];
    const float* bias  = (const float*)d_in[2];
    const int*   ys    = (const int*)d_in[3];
    const int*   elens = (const int*)d_in[4];
    const int*   ylens = (const int*)d_in[5];
    float* out = (float*)d_out;

    cudaFuncSetAttribute(k_main, cudaFuncAttributeMaxDynamicSharedMemorySize, MAIN_SMEM);

    k_convertW<<<256, 256>>>(W);
    k_gather<<<Bz*128, 64>>>(bias, ys);
    k_main<<<Bz*8, 256, MAIN_SMEM>>>(eouts, bias);
    k_dp<<<Bz, 256>>>(ys, elens, ylens);
    k_final<<<1, 32>>>(out);
}

// round 4
// speedup vs baseline: 1.5773x; 1.5773x over previous
#include <cuda_runtime.h>
#include <cuda_bf16.h>
#include <cstdint>

// Problem dims (fixed by the dataset)
#define Bz 32
#define Tz 1000
#define Hz 512
#define Vz 2048
#define Lz 100
#define BTz (Bz*Tz)
#define Sz (2*Lz+1)           // 201
#define NLAB 101              // blank + L labels
#define NEGINF (-1e10f)

// ---------------- device scratch (static: no allocation) ----------------
__device__ __nv_bfloat16 g_Abf[BTz*Hz];        // eouts in bf16      (~32.8 MB)
__device__ __nv_bfloat16 g_Wbf[Vz*Hz];         // W in bf16          (~2.1 MB)
__device__ __nv_bfloat16 g_Wlab[Bz*128*Hz];    // gathered label W rows (padded to 128)
__device__ float         g_blab[Bz*128];       // gathered label biases
__device__ float         g_lse[BTz];           // logsumexp per (b,t)
__device__ float         g_lab[(size_t)BTz*NLAB]; // label log-probs (logit+bias-lse)
__device__ float         g_lossb[Bz];

// ---------------- helpers ----------------
__device__ __forceinline__ void mma16816(float* c, uint32_t a0, uint32_t a1,
                                         uint32_t a2, uint32_t a3,
                                         uint32_t b0, uint32_t b1) {
    asm volatile(
        "mma.sync.aligned.m16n8k16.row.col.f32.bf16.bf16.f32 "
        "{%0,%1,%2,%3}, {%4,%5,%6,%7}, {%8,%9}, {%0,%1,%2,%3};\n"
        : "+f"(c[0]), "+f"(c[1]), "+f"(c[2]), "+f"(c[3])
        : "r"(a0), "r"(a1), "r"(a2), "r"(a3), "r"(b0), "r"(b1));
}

#define A_STR 520   // bf16 elems per A smem row (512 + 8 pad -> conflict-free LDS)
#define W_STR 72    // bf16 elems per W smem row (64 + 8 pad)
#define SMEM_BYTES ((128*A_STR + 2*128*W_STR) * 2)

// ---------------- kernel 1: fp32 -> bf16 conversion ----------------
__global__ void k_convert(const float* __restrict__ e, const float* __restrict__ Wm) {
    const int nA2 = (BTz*Hz)/2, nW2 = (Vz*Hz)/2;
    __nv_bfloat162* A2 = reinterpret_cast<__nv_bfloat162*>(g_Abf);
    __nv_bfloat162* W2 = reinterpret_cast<__nv_bfloat162*>(g_Wbf);
    const float2* e2 = reinterpret_cast<const float2*>(e);
    const float2* w2 = reinterpret_cast<const float2*>(Wm);
    for (int i = blockIdx.x*blockDim.x + threadIdx.x; i < nA2 + nW2;
         i += gridDim.x*blockDim.x) {
        if (i < nA2) { float2 v = e2[i]; A2[i] = __floats2bfloat162_rn(v.x, v.y); }
        else         { float2 v = w2[i-nA2]; W2[i-nA2] = __floats2bfloat162_rn(v.x, v.y); }
    }
}

// ---------------- kernel 2: gather label W rows + biases ----------------
__global__ void k_gather(const float* __restrict__ bias, const int* __restrict__ ys) {
    int idx = blockIdx.x;            // b*128 + j
    int b = idx >> 7, j = idx & 127;
    int v = (j == 0) ? 0 : ((j <= Lz) ? ys[b*Lz + j - 1] : -1);
    uint4* dst = reinterpret_cast<uint4*>(g_Wlab + (size_t)idx*Hz);
    if (v >= 0) {
        const uint4* src = reinterpret_cast<const uint4*>(g_Wbf + (size_t)v*Hz);
        dst[threadIdx.x] = src[threadIdx.x];     // 64 threads x 16B = 1KB row
    } else {
        dst[threadIdx.x] = make_uint4(0u,0u,0u,0u);
    }
    if (threadIdx.x == 0) g_blab[idx] = (v >= 0) ? bias[v] : 0.f;
}

// ---------------- kernel 3: GEMM + online logsumexp (proven round-1 code) ----------------
__global__ __launch_bounds__(256, 1) void k_lse(const float* __restrict__ bias) {
    extern __shared__ __nv_bfloat16 sm[];
    __nv_bfloat16* As = sm;                 // [128][A_STR]
    __nv_bfloat16* Ws = sm + 128*A_STR;     // [2][128][W_STR]
    const int tid = threadIdx.x;
    const int w = tid >> 5, lane = tid & 31, g = lane >> 2, tig = lane & 3;
    const int r0 = blockIdx.x * 128;
    const int rowA = w*16 + g;

    for (int e = tid; e < 128*64; e += 256) {
        int row = e >> 6, c = e & 63;
        *reinterpret_cast<uint4*>(As + row*A_STR + c*8) =
            *reinterpret_cast<const uint4*>(g_Abf + (size_t)(r0+row)*Hz + c*8);
    }

    float M0 = -3e38f, S0 = 0.f, M1 = -3e38f, S1 = 0.f;

    #pragma unroll 1
    for (int nc = 0; nc < Vz/128; nc++) {
        const int vbase = nc * 128;
        uint2 rg[8];
        #pragma unroll
        for (int q = 0; q < 8; q++) {
            int e = tid + q*256; int row = e >> 4, c = e & 15;
            rg[q] = *reinterpret_cast<const uint2*>(g_Wbf + (size_t)(vbase+row)*Hz + c*4);
        }
        #pragma unroll
        for (int q = 0; q < 8; q++) {
            int e = tid + q*256; int row = e >> 4, c = e & 15;
            *reinterpret_cast<uint2*>(Ws + row*W_STR + c*4) = rg[q];
        }
        __syncthreads();

        float acc[16][4];
        #pragma unroll
        for (int i = 0; i < 16; i++) { acc[i][0]=0.f; acc[i][1]=0.f; acc[i][2]=0.f; acc[i][3]=0.f; }

        #pragma unroll 1
        for (int kc = 0; kc < 8; kc++) {
            if (kc < 7) {
                #pragma unroll
                for (int q = 0; q < 8; q++) {
                    int e = tid + q*256; int row = e >> 4, c = e & 15;
                    rg[q] = *reinterpret_cast<const uint2*>(
                        g_Wbf + (size_t)(vbase+row)*Hz + (kc+1)*64 + c*4);
                }
            }
            const __nv_bfloat16* Wb = Ws + (kc & 1) * (128*W_STR);
            #pragma unroll
            for (int ks = 0; ks < 4; ks++) {
                const int kk = kc*64 + ks*16;
                uint32_t a0 = *reinterpret_cast<const uint32_t*>(As + rowA*A_STR + kk + 2*tig);
                uint32_t a1 = *reinterpret_cast<const uint32_t*>(As + (rowA+8)*A_STR + kk + 2*tig);
                uint32_t a2 = *reinterpret_cast<const uint32_t*>(As + rowA*A_STR + kk + 8 + 2*tig);
                uint32_t a3 = *reinterpret_cast<const uint32_t*>(As + (rowA+8)*A_STR + kk + 8 + 2*tig);
                #pragma unroll
                for (int nt = 0; nt < 16; nt++) {
                    uint32_t b0 = *reinterpret_cast<const uint32_t*>(Wb + (nt*8+g)*W_STR + ks*16 + 2*tig);
                    uint32_t b1 = *reinterpret_cast<const uint32_t*>(Wb + (nt*8+g)*W_STR + ks*16 + 8 + 2*tig);
                    mma16816(acc[nt], a0, a1, a2, a3, b0, b1);
                }
            }
            __syncthreads();
            if (kc < 7) {
                __nv_bfloat16* Wd = Ws + ((kc+1) & 1) * (128*W_STR);
                #pragma unroll
                for (int q = 0; q < 8; q++) {
                    int e = tid + q*256; int row = e >> 4, c = e & 15;
                    *reinterpret_cast<uint2*>(Wd + row*W_STR + c*4) = rg[q];
                }
                __syncthreads();
            }
        }

        float m0 = -3e38f, m1 = -3e38f;
        #pragma unroll
        for (int nt = 0; nt < 16; nt++) {
            int v = vbase + nt*8 + 2*tig;
            float bb0 = __ldg(&bias[v]), bb1 = __ldg(&bias[v+1]);
            acc[nt][0] += bb0; acc[nt][1] += bb1; acc[nt][2] += bb0; acc[nt][3] += bb1;
            m0 = fmaxf(m0, fmaxf(acc[nt][0], acc[nt][1]));
            m1 = fmaxf(m1, fmaxf(acc[nt][2], acc[nt][3]));
        }
        float s0 = 0.f, s1 = 0.f;
        #pragma unroll
        for (int nt = 0; nt < 16; nt++) {
            s0 += __expf(acc[nt][0]-m0) + __expf(acc[nt][1]-m0);
            s1 += __expf(acc[nt][2]-m1) + __expf(acc[nt][3]-m1);
        }
        #pragma unroll
        for (int off = 1; off <= 2; off <<= 1) {
            float mo = __shfl_xor_sync(0xffffffffu, m0, off);
            float so = __shfl_xor_sync(0xffffffffu, s0, off);
            float mn = fmaxf(m0, mo);
            s0 = s0*__expf(m0-mn) + so*__expf(mo-mn); m0 = mn;
            mo = __shfl_xor_sync(0xffffffffu, m1, off);
            so = __shfl_xor_sync(0xffffffffu, s1, off);
            mn = fmaxf(m1, mo);
            s1 = s1*__expf(m1-mn) + so*__expf(mo-mn); m1 = mn;
        }
        { float mn = fmaxf(M0, m0); S0 = S0*__expf(M0-mn) + s0*__expf(m0-mn); M0 = mn; }
        { float mn = fmaxf(M1, m1); S1 = S1*__expf(M1-mn) + s1*__expf(m1-mn); M1 = mn; }
    }

    if (tig == 0) {
        g_lse[r0 + rowA]     = M0 + __logf(S0);
        g_lse[r0 + rowA + 8] = M1 + __logf(S1);
    }
}

// ---------------- kernel 4: label-logit GEMM (N=128 padded labels) ----------------
__global__ __launch_bounds__(256, 1) void k_lab() {
    extern __shared__ __nv_bfloat16 sm[];
    __nv_bfloat16* As = sm;
    __nv_bfloat16* Ws = sm + 128*A_STR;
    const int tid = threadIdx.x;
    const int w = tid >> 5, lane = tid & 31, g = lane >> 2, tig = lane & 3;
    const int mc = blockIdx.x, b = blockIdx.y;
    const int t0 = mc * 128;
    const __nv_bfloat16* Wsrc = g_Wlab + (size_t)b*128*Hz;

    for (int e = tid; e < 128*64; e += 256) {
        int row = e >> 6, c = e & 63;
        int t = t0 + row; if (t > Tz-1) t = Tz-1;
        *reinterpret_cast<uint4*>(As + row*A_STR + c*8) =
            *reinterpret_cast<const uint4*>(g_Abf + (size_t)(b*Tz + t)*Hz + c*8);
    }

    uint2 rg[8];
    #pragma unroll
    for (int q = 0; q < 8; q++) {
        int e = tid + q*256; int row = e >> 4, c = e & 15;
        rg[q] = *reinterpret_cast<const uint2*>(Wsrc + (size_t)row*Hz + c*4);
    }
    #pragma unroll
    for (int q = 0; q < 8; q++) {
        int e = tid + q*256; int row = e >> 4, c = e & 15;
        *reinterpret_cast<uint2*>(Ws + row*W_STR + c*4) = rg[q];
    }
    __syncthreads();

    float acc[16][4];
    #pragma unroll
    for (int i = 0; i < 16; i++) { acc[i][0]=0.f; acc[i][1]=0.f; acc[i][2]=0.f; acc[i][3]=0.f; }

    #pragma unroll 1
    for (int kc = 0; kc < 8; kc++) {
        if (kc < 7) {
            #pragma unroll
            for (int q = 0; q < 8; q++) {
                int e = tid + q*256; int row = e >> 4, c = e & 15;
                rg[q] = *reinterpret_cast<const uint2*>(Wsrc + (size_t)row*Hz + (kc+1)*64 + c*4);
            }
        }
        const __nv_bfloat16* Wb = Ws + (kc & 1) * (128*W_STR);
        const int rowA = w*16 + g;
        #pragma unroll
        for (int ks = 0; ks < 4; ks++) {
            const int kk = kc*64 + ks*16;
            uint32_t a0 = *reinterpret_cast<const uint32_t*>(As + rowA*A_STR + kk + 2*tig);
            uint32_t a1 = *reinterpret_cast<const uint32_t*>(As + (rowA+8)*A_STR + kk + 2*tig);
            uint32_t a2 = *reinterpret_cast<const uint32_t*>(As + rowA*A_STR + kk + 8 + 2*tig);
            uint32_t a3 = *reinterpret_cast<const uint32_t*>(As + (rowA+8)*A_STR + kk + 8 + 2*tig);
            #pragma unroll
            for (int nt = 0; nt < 16; nt++) {
                uint32_t b0 = *reinterpret_cast<const uint32_t*>(Wb + (nt*8+g)*W_STR + ks*16 + 2*tig);
                uint32_t b1 = *reinterpret_cast<const uint32_t*>(Wb + (nt*8+g)*W_STR + ks*16 + 8 + 2*tig);
                mma16816(acc[nt], a0, a1, a2, a3, b0, b1);
            }
        }
        __syncthreads();
        if (kc < 7) {
            __nv_bfloat16* Wd = Ws + ((kc+1) & 1) * (128*W_STR);
            #pragma unroll
            for (int q = 0; q < 8; q++) {
                int e = tid + q*256; int row = e >> 4, c = e & 15;
                *reinterpret_cast<uint2*>(Wd + row*W_STR + c*4) = rg[q];
            }
            __syncthreads();
        }
    }

    const int rowA = w*16 + g;
    int ta = t0 + rowA, tb = ta + 8;
    float lseA = (ta < Tz) ? g_lse[b*Tz + ta] : 0.f;
    float lseB = (tb < Tz) ? g_lse[b*Tz + tb] : 0.f;
    #pragma unroll
    for (int nt = 0; nt < 16; nt++) {
        int c0 = nt*8 + 2*tig, c1 = c0 + 1;
        float bb0 = g_blab[b*128 + c0], bb1 = g_blab[b*128 + c1];
        if (ta < Tz) {
            if (c0 < NLAB) g_lab[(size_t)(b*Tz+ta)*NLAB + c0] = acc[nt][0] + bb0 - lseA;
            if (c1 < NLAB) g_lab[(size_t)(b*Tz+ta)*NLAB + c1] = acc[nt][1] + bb1 - lseA;
        }
        if (tb < Tz) {
            if (c0 < NLAB) g_lab[(size_t)(b*Tz+tb)*NLAB + c0] = acc[nt][2] + bb0 - lseB;
            if (c1 < NLAB) g_lab[(size_t)(b*Tz+tb)*NLAB + c1] = acc[nt][3] + bb1 - lseB;
        }
    }
}

// ---------------- kernel 5: CTC forward DP (register trapezoid, 1 shfl/step) ----------------
// 7 warps x 64 states (32 own + 32 left halo), interleaved: lane holds
// (even s, odd s) = (r0, r1) with s0 = 32w-32+2*lane. Blank (even) states need
// only r1[lane-1]; label (odd) states need r0 (same lane) + r1[lane-1]:
// ONE shfl.up per step, no block sync. Validity shrinks 2 states/step over the
// 32-state halo -> halo exchange via smem every 16 steps.
__global__ __launch_bounds__(224) void k_dp(const int* __restrict__ ys,
                                            const int* __restrict__ elens,
                                            const int* __restrict__ ylens) {
    __shared__ float sA[224];
    const int b = blockIdx.x;
    const int tid = threadIdx.x, w = tid >> 5, lane = tid & 31;
    const int elen = elens[b], ylen = ylens[b];
    const int smax = 2*ylen + 1;
    const int s0 = 32*w - 32 + 2*lane;
    const int s1 = s0 + 1;
    const bool v0 = (s0 >= 0) && (s0 < smax);
    const bool v1 = (s1 >= 0) && (s1 < smax);
    const int yidx = (s1 >= 1) ? (s1 >> 1) : 0;          // ys index for s1's skip test
    const int j1c  = min(max(yidx + 1, 0), NLAB - 1);    // lab column for s1 (clamped)
    bool skip1 = false;
    if (s1 >= 3 && yidx >= 1 && yidx <= Lz - 1)
        skip1 = (ys[b*Lz + yidx] != ys[b*Lz + yidx - 1]);
    const float* lab = g_lab + (size_t)b*Tz*NLAB;

    float r0 = (v0 && s0 == 0) ? lab[0] : NEGINF;
    float r1 = (v1 && s1 == 1) ? lab[1] : NEGINF;

    // 4-deep label-logprob prefetch pipeline (t = 1..4)
    float pB0 = __ldg(lab + 1*NLAB), p10 = __ldg(lab + 1*NLAB + j1c);
    float pB1 = __ldg(lab + 2*NLAB), p11 = __ldg(lab + 2*NLAB + j1c);
    float pB2 = __ldg(lab + 3*NLAB), p12 = __ldg(lab + 3*NLAB + j1c);
    float pB3 = __ldg(lab + 4*NLAB), p13 = __ldg(lab + 4*NLAB + j1c);

    auto step = [&](int t) {
        float r1m = __shfl_up_sync(0xffffffffu, r1, 1);
        if (lane == 0) r1m = NEGINF;
        // even (blank): preds s0, s0-1(=r1m)
        float m0 = fmaxf(r0, r1m);
        float n0 = m0 + __logf(__expf(r0 - m0) + __expf(r1m - m0)) + pB0;
        // odd (label): preds s1(=r1), s1-1(=r0), s1-2(=r1m, skip-gated)
        float x2 = skip1 ? r1m : NEGINF;
        float m1 = fmaxf(fmaxf(r1, r0), x2);
        float n1 = m1 + __logf(__expf(r1 - m1) + __expf(r0 - m1) + __expf(x2 - m1)) + p10;
        r0 = v0 ? n0 : NEGINF;
        r1 = v1 ? n1 : NEGINF;
        pB0 = pB1; p10 = p11; pB1 = pB2; p11 = p12; pB2 = pB3; p12 = p13;
        int tn = t + 4; if (tn > elen - 1) tn = elen - 1;
        const float* q = lab + (size_t)tn * NLAB;
        pB3 = __ldg(q); p13 = __ldg(q + j1c);
    };

    int t = 1;
    while (t < elen) {
        int rem = elen - t;
        if (rem >= 16) {
            #pragma unroll
            for (int k2 = 0; k2 < 16; k2++) step(t + k2);
            t += 16;
        } else {
            #pragma unroll 1
            for (int k2 = 0; k2 < rem; k2++) step(t + k2);
            t += rem;
        }
        // halo exchange: own windows (lanes 16..31) -> smem; refresh halo (lanes 0..15)
        if (lane >= 16) { sA[s0] = r0; sA[s1] = r1; }
        __syncthreads();
        if (lane < 16 && w > 0) { r0 = sA[s0]; r1 = sA[s1]; }
        __syncthreads();
    }

    // own windows for time elen-1 are in sA from the final exchange
    if (tid == 0) {
        float last = sA[2*ylen];
        float prev = sA[2*ylen - 1];
        float m = fmaxf(last, prev);
        float loss = -(m + __logf(__expf(last - m) + __expf(prev - m)));
        g_lossb[b] = (loss < -0.5f*NEGINF) ? loss : 0.f;
    }
}

// ---------------- kernel 6: deterministic finalize ----------------
__global__ void k_final(float* __restrict__ out) {
    if (threadIdx.x == 0 && blockIdx.x == 0) {
        float s = 0.f;
        for (int b = 0; b < Bz; b++) s += g_lossb[b];
        out[0] = s / (float)Bz;
    }
}

// ---------------- entry ----------------
extern "C" void kernel_launch(void* const* d_in, const int* in_sizes, int n_in,
                              void* d_out, int out_size) {
    const float* eouts = (const float*)d_in[0];
    const float* W     = (const float*)d_in[1];
    const float* bias  = (const float*)d_in[2];
    const int*   ys    = (const int*)d_in[3];
    const int*   elens = (const int*)d_in[4];
    const int*   ylens = (const int*)d_in[5];
    float* out = (float*)d_out;

    cudaFuncSetAttribute(k_lse, cudaFuncAttributeMaxDynamicSharedMemorySize, SMEM_BYTES);
    cudaFuncSetAttribute(k_lab, cudaFuncAttributeMaxDynamicSharedMemorySize, SMEM_BYTES);

    k_convert<<<2048, 256>>>(eouts, W);
    k_gather<<<Bz*128, 64>>>(bias, ys);
    k_lse<<<BTz/128, 256, SMEM_BYTES>>>(bias);
    k_lab<<<dim3((Tz + 127)/128, Bz), 256, SMEM_BYTES>>>();
    k_dp<<<Bz, 224>>>(ys, elens, ylens);
    k_final<<<1, 32>>>(out);
}

// round 5
// speedup vs baseline: 1.7183x; 1.0894x over previous
#include <cuda_runtime.h>
#include <cuda_bf16.h>
#include <cstdint>

// Problem dims (fixed by the dataset)
#define Bz 32
#define Tz 1000
#define Hz 512
#define Vz 2048
#define Lz 100
#define BTz (Bz*Tz)
#define Sz (2*Lz+1)           // 201
#define NLAB 101              // blank + L labels
#define NEGINF (-1e10f)

// ---------------- device scratch (static: no allocation) ----------------
__device__ __nv_bfloat16 g_Wbf[Vz*Hz];         // W in bf16 (2 MB)
__device__ __nv_bfloat16 g_Wlab[Bz*128*Hz];    // gathered label W rows (padded to 128)
__device__ float         g_blab[Bz*128];       // gathered label biases
__device__ float         g_lab[(size_t)BTz*NLAB]; // label log-probs (logit+bias-lse)
__device__ float         g_lossb[Bz];

// ---------------- helpers ----------------
__device__ __forceinline__ void mma16816(float* c, uint32_t a0, uint32_t a1,
                                         uint32_t a2, uint32_t a3,
                                         uint32_t b0, uint32_t b1) {
    asm volatile(
        "mma.sync.aligned.m16n8k16.row.col.f32.bf16.bf16.f32 "
        "{%0,%1,%2,%3}, {%4,%5,%6,%7}, {%8,%9}, {%0,%1,%2,%3};\n"
        : "+f"(c[0]), "+f"(c[1]), "+f"(c[2]), "+f"(c[3])
        : "r"(a0), "r"(a1), "r"(a2), "r"(a3), "r"(b0), "r"(b1));
}

#define A_STR 520   // bf16 elems per A smem row (512 + 8 pad -> conflict-free LDS)
#define W_STR 72    // bf16 elems per W smem row (64 + 8 pad)
#define A_BYTES  (128*A_STR*2)                  // 133120
#define W2_BYTES (2*128*W_STR*2)                // 36864
#define BIAS_OFF (A_BYTES + W2_BYTES)           // 169984
#define SL_OFF   (BIAS_OFF + Vz*4)              // 178176
#define MAIN_SMEM (SL_OFF + 2*128*8)            // 180224

// ---------------- kernel 1: fp32 -> bf16 conversion (W only) ----------------
__global__ void k_convertW(const float* __restrict__ Wm) {
    const int nW2 = (Vz*Hz)/2;
    __nv_bfloat162* W2 = reinterpret_cast<__nv_bfloat162*>(g_Wbf);
    const float2* w2 = reinterpret_cast<const float2*>(Wm);
    for (int i = blockIdx.x*blockDim.x + threadIdx.x; i < nW2; i += gridDim.x*blockDim.x) {
        float2 v = w2[i]; W2[i] = __floats2bfloat162_rn(v.x, v.y);
    }
}

// ---------------- kernel 2: gather label W rows + biases ----------------
__global__ void k_gather(const float* __restrict__ bias, const int* __restrict__ ys) {
    int idx = blockIdx.x;            // b*128 + j
    int b = idx >> 7, j = idx & 127;
    int v = (j == 0) ? 0 : ((j <= Lz) ? ys[b*Lz + j - 1] : -1);
    uint4* dst = reinterpret_cast<uint4*>(g_Wlab + (size_t)idx*Hz);
    if (v >= 0) {
        const uint4* src = reinterpret_cast<const uint4*>(g_Wbf + (size_t)v*Hz);
        dst[threadIdx.x] = src[threadIdx.x];
    } else {
        dst[threadIdx.x] = make_uint4(0u,0u,0u,0u);
    }
    if (threadIdx.x == 0) g_blab[idx] = (v >= 0) ? bias[v] : 0.f;
}

// ---------------- kernel 3: fused GEMM + online LSE + label log-probs ----------------
// Grid: Bz*8 CTAs; CTA = (b, tc): 125 time rows (padded to 128 via clamp; duplicate
// writes idempotent). Warps tiled 4M x 2N: warp (wm, wn) owns rows wm*32..+31,
// cols wn*64..+63 of each 128-col chunk. Per-(row, half) online LSE in registers
// over 16 vocab chunks; one smem merge; 17th chunk = label GEMM -> g_lab.
__global__ __launch_bounds__(256, 1) void k_main(const float* __restrict__ eouts,
                                                 const float* __restrict__ bias) {
    extern __shared__ char smc[];
    __nv_bfloat16* As = reinterpret_cast<__nv_bfloat16*>(smc);
    __nv_bfloat16* Ws = As + 128*A_STR;
    float*  bias_s = reinterpret_cast<float*>(smc + BIAS_OFF);
    float2* sL     = reinterpret_cast<float2*>(smc + SL_OFF);
    const int tid = threadIdx.x;
    const int w = tid >> 5, lane = tid & 31, g = lane >> 2, tig = lane & 3;
    const int wm = w >> 1, wn = w & 1;
    const int rA0 = wm*32 + g;       // base row (of 4: rA0+8i)
    const int nb  = wn*64;           // base col within chunk
    const int b  = blockIdx.x >> 3;
    const int t0 = (blockIdx.x & 7) * 125;

    // bias -> smem (512 float4)
    for (int i = tid; i < Vz/4; i += 256)
        reinterpret_cast<float4*>(bias_s)[i] = reinterpret_cast<const float4*>(bias)[i];

    // A tile: 128 rows x 512, fp32 -> bf16 inline, clamped t
    for (int e = tid; e < 128*64; e += 256) {
        int row = e >> 6, c = e & 63;
        int t = t0 + row; if (t > Tz-1) t = Tz-1;
        const float4* src = reinterpret_cast<const float4*>(eouts + (size_t)(b*Tz + t)*Hz + c*8);
        float4 v0 = src[0], v1 = src[1];
        __nv_bfloat162 p0 = __floats2bfloat162_rn(v0.x, v0.y);
        __nv_bfloat162 p1 = __floats2bfloat162_rn(v0.z, v0.w);
        __nv_bfloat162 p2 = __floats2bfloat162_rn(v1.x, v1.y);
        __nv_bfloat162 p3 = __floats2bfloat162_rn(v1.z, v1.w);
        uint4 pk = make_uint4(*reinterpret_cast<uint32_t*>(&p0), *reinterpret_cast<uint32_t*>(&p1),
                              *reinterpret_cast<uint32_t*>(&p2), *reinterpret_cast<uint32_t*>(&p3));
        *reinterpret_cast<uint4*>(As + row*A_STR + c*8) = pk;
    }

    float M[4] = {-3e38f,-3e38f,-3e38f,-3e38f};
    float S[4] = {0.f,0.f,0.f,0.f};
    float lsev[4];

    #pragma unroll 1
    for (int nc = 0; nc < 17; nc++) {
        if (nc == 16) {
            // merge per-half LSE across the wn pair (rows identical for wn=0/1)
            if (tig == 0) {
                #pragma unroll
                for (int i = 0; i < 4; i++)
                    sL[wn*128 + rA0 + 8*i] = make_float2(M[i], S[i]);
            }
            __syncthreads();
            #pragma unroll
            for (int i = 0; i < 4; i++) {
                float2 o = sL[(wn^1)*128 + rA0 + 8*i];
                float mn = fmaxf(M[i], o.x);
                float ss = S[i]*__expf(M[i]-mn) + o.y*__expf(o.x-mn);
                lsev[i] = mn + __logf(ss);
            }
        }
        const __nv_bfloat16* wsrc = (nc < 16) ? (g_Wbf + (size_t)(nc*128)*Hz)
                                              : (g_Wlab + (size_t)b*128*Hz);
        // stage K-chunk 0 into buffer 0
        uint2 rg[8];
        #pragma unroll
        for (int q = 0; q < 8; q++) {
            int e = tid + q*256; int row = e >> 4, c = e & 15;
            rg[q] = *reinterpret_cast<const uint2*>(wsrc + (size_t)row*Hz + c*4);
        }
        #pragma unroll
        for (int q = 0; q < 8; q++) {
            int e = tid + q*256; int row = e >> 4, c = e & 15;
            *reinterpret_cast<uint2*>(Ws + row*W_STR + c*4) = rg[q];
        }
        __syncthreads();

        float acc[2][8][4];
        #pragma unroll
        for (int mt = 0; mt < 2; mt++)
            #pragma unroll
            for (int nt = 0; nt < 8; nt++) {
                acc[mt][nt][0]=0.f; acc[mt][nt][1]=0.f; acc[mt][nt][2]=0.f; acc[mt][nt][3]=0.f;
            }

        #pragma unroll 1
        for (int kc = 0; kc < 8; kc++) {
            if (kc < 7) {
                #pragma unroll
                for (int q = 0; q < 8; q++) {
                    int e = tid + q*256; int row = e >> 4, c = e & 15;
                    rg[q] = *reinterpret_cast<const uint2*>(wsrc + (size_t)row*Hz + (kc+1)*64 + c*4);
                }
            }
            const __nv_bfloat16* Wb = Ws + (kc & 1) * (128*W_STR);
            #pragma unroll
            for (int ks = 0; ks < 4; ks++) {
                const int kk = kc*64 + ks*16;
                uint32_t a0[2], a1[2], a2[2], a3[2];
                #pragma unroll
                for (int mt = 0; mt < 2; mt++) {
                    const int R = rA0 + 16*mt;
                    a0[mt] = *reinterpret_cast<const uint32_t*>(As + R*A_STR + kk + 2*tig);
                    a1[mt] = *reinterpret_cast<const uint32_t*>(As + (R+8)*A_STR + kk + 2*tig);
                    a2[mt] = *reinterpret_cast<const uint32_t*>(As + R*A_STR + kk + 8 + 2*tig);
                    a3[mt] = *reinterpret_cast<const uint32_t*>(As + (R+8)*A_STR + kk + 8 + 2*tig);
                }
                #pragma unroll
                for (int nt = 0; nt < 8; nt++) {
                    uint32_t b0 = *reinterpret_cast<const uint32_t*>(Wb + (nb+nt*8+g)*W_STR + ks*16 + 2*tig);
                    uint32_t b1 = *reinterpret_cast<const uint32_t*>(Wb + (nb+nt*8+g)*W_STR + ks*16 + 8 + 2*tig);
                    mma16816(acc[0][nt], a0[0], a1[0], a2[0], a3[0], b0, b1);
                    mma16816(acc[1][nt], a0[1], a1[1], a2[1], a3[1], b0, b1);
                }
            }
            __syncthreads();
            if (kc < 7) {
                __nv_bfloat16* Wd = Ws + ((kc+1) & 1) * (128*W_STR);
                #pragma unroll
                for (int q = 0; q < 8; q++) {
                    int e = tid + q*256; int row = e >> 4, c = e & 15;
                    *reinterpret_cast<uint2*>(Wd + row*W_STR + c*4) = rg[q];
                }
                __syncthreads();
            }
        }

        if (nc < 16) {
            // vocab epilogue: bias + per-(row,half) chunk (max, sumexp) -> online merge
            float bm[4] = {-3e38f,-3e38f,-3e38f,-3e38f};
            #pragma unroll
            for (int nt = 0; nt < 8; nt++) {
                int c0 = nc*128 + nb + nt*8 + 2*tig;
                float bb0 = bias_s[c0], bb1 = bias_s[c0+1];
                #pragma unroll
                for (int mt = 0; mt < 2; mt++) {
                    acc[mt][nt][0]+=bb0; acc[mt][nt][1]+=bb1;
                    acc[mt][nt][2]+=bb0; acc[mt][nt][3]+=bb1;
                    bm[2*mt]   = fmaxf(bm[2*mt],   fmaxf(acc[mt][nt][0], acc[mt][nt][1]));
                    bm[2*mt+1] = fmaxf(bm[2*mt+1], fmaxf(acc[mt][nt][2], acc[mt][nt][3]));
                }
            }
            float bs[4] = {0.f,0.f,0.f,0.f};
            #pragma unroll
            for (int nt = 0; nt < 8; nt++)
                #pragma unroll
                for (int mt = 0; mt < 2; mt++) {
                    bs[2*mt]   += __expf(acc[mt][nt][0]-bm[2*mt])   + __expf(acc[mt][nt][1]-bm[2*mt]);
                    bs[2*mt+1] += __expf(acc[mt][nt][2]-bm[2*mt+1]) + __expf(acc[mt][nt][3]-bm[2*mt+1]);
                }
            #pragma unroll
            for (int off = 1; off <= 2; off <<= 1) {
                #pragma unroll
                for (int i = 0; i < 4; i++) {
                    float mo = __shfl_xor_sync(0xffffffffu, bm[i], off);
                    float so = __shfl_xor_sync(0xffffffffu, bs[i], off);
                    float mn = fmaxf(bm[i], mo);
                    bs[i] = bs[i]*__expf(bm[i]-mn) + so*__expf(mo-mn); bm[i] = mn;
                }
            }
            #pragma unroll
            for (int i = 0; i < 4; i++) {
                float mn = fmaxf(M[i], bm[i]);
                S[i] = S[i]*__expf(M[i]-mn) + bs[i]*__expf(bm[i]-mn); M[i] = mn;
            }
        } else {
            // label epilogue: lp = logit + blab - lse -> g_lab
            #pragma unroll
            for (int i = 0; i < 4; i++) {
                int R = rA0 + 8*i;
                int t = t0 + R; if (t > Tz-1) t = Tz-1;
                float* ptr = g_lab + (size_t)(b*Tz + t)*NLAB;
                const int mt = i >> 1, q = (i & 1)*2;
                #pragma unroll
                for (int nt = 0; nt < 8; nt++) {
                    int c0 = nb + nt*8 + 2*tig;
                    if (c0 < NLAB)
                        ptr[c0]   = acc[mt][nt][q]   + g_blab[b*128 + c0]   - lsev[i];
                    if (c0+1 < NLAB)
                        ptr[c0+1] = acc[mt][nt][q+1] + g_blab[b*128 + c0+1] - lsev[i];
                }
            }
        }
    }
}

// ---------------- kernel 4: CTC forward DP (register trapezoid + smem label stage) ----------------
// 7 warps x 64 states (32 own + 32 left halo), interleaved (even,odd) per lane.
// ONE shfl.up per step; label log-probs for each 16-step block staged into smem
// (contiguous 6.4KB copy), read as conflict-free stride-1 LDS with 1-step prefetch.
__global__ __launch_bounds__(224) void k_dp(const int* __restrict__ ys,
                                            const int* __restrict__ elens,
                                            const int* __restrict__ ylens) {
    __shared__ float sA[224];
    __shared__ float sLab[16*NLAB];
    const int b = blockIdx.x;
    const int tid = threadIdx.x, w = tid >> 5, lane = tid & 31;
    const int elen = elens[b], ylen = ylens[b];
    const int smax = 2*ylen + 1;
    const int s0 = 32*w - 32 + 2*lane;
    const int s1 = s0 + 1;
    const bool v0 = (s0 >= 0) && (s0 < smax);
    const bool v1 = (s1 >= 0) && (s1 < smax);
    const int yidx = (s1 >= 1) ? (s1 >> 1) : 0;
    const int j1c  = min(max(yidx + 1, 0), NLAB - 1);
    bool skip1 = false;
    if (s1 >= 3 && yidx >= 1 && yidx <= Lz - 1)
        skip1 = (ys[b*Lz + yidx] != ys[b*Lz + yidx - 1]);
    const float* lab = g_lab + (size_t)b*Tz*NLAB;

    float r0 = (v0 && s0 == 0) ? __ldg(lab + 0) : NEGINF;
    float r1 = (v1 && s1 == 1) ? __ldg(lab + 1) : NEGINF;

    int t = 1;
    while (t < elen) {
        const int n = min(16, elen - t);
        __syncthreads();                       // sLab reuse guard
        for (int i = tid; i < n*NLAB; i += 224)
            sLab[i] = lab[(size_t)t*NLAB + i]; // fully contiguous block copy
        __syncthreads();

        float pB = sLab[0], p1 = sLab[j1c];
        #pragma unroll 4
        for (int k = 0; k < n; k++) {
            float pBn = 0.f, p1n = 0.f;
            if (k + 1 < n) { pBn = sLab[(k+1)*NLAB]; p1n = sLab[(k+1)*NLAB + j1c]; }
            float r1m = __shfl_up_sync(0xffffffffu, r1, 1);
            if (lane == 0) r1m = NEGINF;
            // even (blank): preds s0, s0-1(=r1m)
            float m0 = fmaxf(r0, r1m);
            float n0 = m0 + __logf(__expf(r0 - m0) + __expf(r1m - m0)) + pB;
            // odd (label): preds s1(=r1), s1-1(=r0), s1-2(=r1m, skip-gated)
            float x2 = skip1 ? r1m : NEGINF;
            float m1 = fmaxf(fmaxf(r1, r0), x2);
            float n1 = m1 + __logf(__expf(r1 - m1) + __expf(r0 - m1) + __expf(x2 - m1)) + p1;
            r0 = v0 ? n0 : NEGINF;
            r1 = v1 ? n1 : NEGINF;
            pB = pBn; p1 = p1n;
        }
        t += n;
        // halo exchange: own windows (lanes 16..31) -> smem; refresh halo (lanes 0..15)
        if (lane >= 16) { sA[s0] = r0; sA[s1] = r1; }
        __syncthreads();
        if (lane < 16 && w > 0) { r0 = sA[s0]; r1 = sA[s1]; }
    }

    if (tid == 0) {
        float last = sA[2*ylen];
        float prev = sA[2*ylen - 1];
        float m = fmaxf(last, prev);
        float loss = -(m + __logf(__expf(last - m) + __expf(prev - m)));
        g_lossb[b] = (loss < -0.5f*NEGINF) ? loss : 0.f;
    }
}

// ---------------- kernel 5: deterministic finalize ----------------
__global__ void k_final(float* __restrict__ out) {
    if (threadIdx.x == 0 && blockIdx.x == 0) {
        float s = 0.f;
        for (int b = 0; b < Bz; b++) s += g_lossb[b];
        out[0] = s / (float)Bz;
    }
}

// ---------------- entry ----------------
extern "C" void kernel_launch(void* const* d_in, const int* in_sizes, int n_in,
                              void* d_out, int out_size) {
    const float* eouts = (const float*)d_in[0];
    const float* W     = (const float*)d_in[1];
    const float* bias  = (const float*)d_in[2];
    const int*   ys    = (const int*)d_in[3];
    const int*   elens = (const int*)d_in[4];
    const int*   ylens = (const int*)d_in[5];
    float* out = (float*)d_out;

    cudaFuncSetAttribute(k_main, cudaFuncAttributeMaxDynamicSharedMemorySize, MAIN_SMEM);

    k_convertW<<<256, 256>>>(W);
    k_gather<<<Bz*128, 64>>>(bias, ys);
    k_main<<<Bz*8, 256, MAIN_SMEM>>>(eouts, bias);
    k_dp<<<Bz, 224>>>(ys, elens, ylens);
    k_final<<<1, 32>>>(out);
}